// round 8
// baseline (speedup 1.0000x reference)
#include <cuda_runtime.h>
#include <cuda_bf16.h>
#include <cuda_fp16.h>
#include <cstdint>
#include <cstddef>

#define NN 50000
#define EE 800000
#define FF 256
#define LL 3
#define NB 196   // ceil(NN/256)

// ---------------- scratch (device globals) ----------------
__device__ float g_deg[NN];
__device__ float g_dinv[NN];
__device__ int   g_cnt[NN];
__device__ int   g_rowptr[NN + 1];
__device__ int   g_cursor[NN];
__device__ int   g_bsum[NB];
__device__ int   g_boff[NB];
__device__ int   g_csrc[EE];
__device__ float g_cw[EE];
__device__ __half g_h[(size_t)NN * FF];      // layer0: h = x@Wi in fp16
__device__ float  g_y[(size_t)NN * FF];      // layer0: y = x@Wr + b in fp32
__device__ __half g_xf16[(size_t)NN * FF];   // current activations, fp16 (agg gather)
// z = agg(x) bf16 splits (GEMM A-part 1 for commuted layers)
__device__ __nv_bfloat16 g_zhi[(size_t)NN * FF];
__device__ __nv_bfloat16 g_zlo[(size_t)NN * FF];
// ping-pong activation splits (GEMM A / A-part 2)
__device__ __nv_bfloat16 g_xAhi[(size_t)NN * FF];
__device__ __nv_bfloat16 g_xAlo[(size_t)NN * FF];
__device__ __nv_bfloat16 g_xBhi[(size_t)NN * FF];
__device__ __nv_bfloat16 g_xBlo[(size_t)NN * FF];
// fused transposed weights: [layer][512][256]; rows 0-255 = Wi^T, 256-511 = Wr^T
__device__ __nv_bfloat16 g_Bhi[3 * 512 * 256];
__device__ __nv_bfloat16 g_Blo[3 * 512 * 256];

// ---------------- helpers ----------------
__device__ __forceinline__ uint32_t smem_u32(const void* p) {
    uint32_t a;
    asm("{ .reg .u64 t; cvta.to.shared.u64 t, %1; cvt.u32.u64 %0, t; }"
        : "=r"(a) : "l"(p));
    return a;
}
__device__ __forceinline__ uint32_t swz(uint32_t off) { return off ^ ((off >> 3) & 0x70); }

__device__ __forceinline__ void ldmx4(uint32_t* r, uint32_t addr) {
    asm volatile("ldmatrix.sync.aligned.m8n8.x4.shared.b16 {%0,%1,%2,%3}, [%4];"
                 : "=r"(r[0]), "=r"(r[1]), "=r"(r[2]), "=r"(r[3]) : "r"(addr));
}
__device__ __forceinline__ void mma16816(float* c, const uint32_t* a, const uint32_t* b) {
    asm volatile(
        "mma.sync.aligned.m16n8k16.row.col.f32.bf16.bf16.f32 "
        "{%0,%1,%2,%3}, {%4,%5,%6,%7}, {%8,%9}, {%0,%1,%2,%3};"
        : "+f"(c[0]), "+f"(c[1]), "+f"(c[2]), "+f"(c[3])
        : "r"(a[0]), "r"(a[1]), "r"(a[2]), "r"(a[3]), "r"(b[0]), "r"(b[1]));
}
__device__ __forceinline__ uint32_t pack_bf16(__nv_bfloat16 a, __nv_bfloat16 b) {
    return (uint32_t)__bfloat16_as_ushort(a) | ((uint32_t)__bfloat16_as_ushort(b) << 16);
}
__device__ __forceinline__ void cp16(uint32_t dst, const void* src, uint32_t valid) {
    asm volatile("cp.async.cg.shared.global [%0], [%1], 16, %2;"
                 :: "r"(dst), "l"(src), "r"(valid ? 16u : 0u));
}
#define CP_COMMIT() asm volatile("cp.async.commit_group;" ::: "memory")
template <int N> __device__ __forceinline__ void cp_wait() {
    asm volatile("cp.async.wait_group %0;" :: "n"(N) : "memory");
}

// ---------------- setup kernels ----------------
__global__ void hist_kernel(const int* __restrict__ src, const int* __restrict__ dst,
                            const float* __restrict__ w) {
    int e = blockIdx.x * blockDim.x + threadIdx.x;
    if (e >= EE) return;
    int d = dst[e];
    atomicAdd(&g_deg[d], w[e]);
    atomicAdd(&g_cnt[d], 1);
}

__global__ void dinv_kernel() {
    int n = blockIdx.x * blockDim.x + threadIdx.x;
    if (n >= NN) return;
    float d = g_deg[n];
    g_dinv[n] = (d > 0.f) ? rsqrtf(d) : 0.f;
}

__global__ void scan_local() {
    __shared__ int sh[256];
    int b = blockIdx.x, tid = threadIdx.x, i = b * 256 + tid;
    int v = (i < NN) ? g_cnt[i] : 0;
    sh[tid] = v;
    __syncthreads();
    #pragma unroll
    for (int off = 1; off < 256; off <<= 1) {
        int t2 = (tid >= off) ? sh[tid - off] : 0;
        __syncthreads();
        sh[tid] += t2;
        __syncthreads();
    }
    if (i < NN) g_rowptr[i] = sh[tid];
    if (tid == 255) g_bsum[b] = sh[255];
}
__global__ void scan_blocks() {
    __shared__ int sh[256];
    int tid = threadIdx.x;
    int v = (tid < NB) ? g_bsum[tid] : 0;
    sh[tid] = v;
    __syncthreads();
    #pragma unroll
    for (int off = 1; off < 256; off <<= 1) {
        int t2 = (tid >= off) ? sh[tid - off] : 0;
        __syncthreads();
        sh[tid] += t2;
        __syncthreads();
    }
    if (tid < NB) g_boff[tid] = sh[tid] - v;
    if (tid == NB - 1) g_rowptr[NN] = sh[tid];
}
__global__ void scan_finish() {
    int i = blockIdx.x * 256 + threadIdx.x;
    if (i >= NN) return;
    int excl = g_rowptr[i] - g_cnt[i] + g_boff[blockIdx.x];
    g_rowptr[i] = excl;
    g_cursor[i] = excl;
}

__global__ void fill_kernel(const int* __restrict__ src, const int* __restrict__ dst,
                            const float* __restrict__ w) {
    int e = blockIdx.x * blockDim.x + threadIdx.x;
    if (e >= EE) return;
    int s = src[e];
    int d = dst[e];
    int pos = atomicAdd(&g_cursor[d], 1);
    g_csrc[pos] = s;
    g_cw[pos] = g_dinv[s] * w[e] * g_dinv[d];
}

__global__ void convert_w_kernel(const float* __restrict__ Wi, const float* __restrict__ Wr) {
    int idx = blockIdx.x * blockDim.x + threadIdx.x;
    if (idx >= 3 * 512 * 256) return;
    int l = idx >> 17;
    int n = (idx >> 8) & 511;
    int k = idx & 255;
    const float* W = (n < 256) ? Wi : Wr;
    int nn = n & 255;
    float v = W[(size_t)l * FF * FF + (size_t)k * FF + nn];
    __nv_bfloat16 hi = __float2bfloat16(v);
    __nv_bfloat16 lo = __float2bfloat16(v - __bfloat162float(hi));
    g_Bhi[idx] = hi;
    g_Blo[idx] = lo;
}

// split layer-0 activations into buffer A
__global__ void convert_x_kernel(const float* __restrict__ x) {
    int idx = blockIdx.x * blockDim.x + threadIdx.x;
    if (idx >= NN * FF) return;
    float v = x[idx];
    __nv_bfloat16 hi = __float2bfloat16(v);
    __nv_bfloat16 lo = __float2bfloat16(v - __bfloat162float(hi));
    g_xAhi[idx] = hi;
    g_xAlo[idx] = lo;
}

// ---------------- HMMA bf16-split GEMM (cp.async 2-stage pipeline) ----------------
// FORM 0: layer0.   [H(fp16) | Y(fp32)+bias] = A1[M,256] @ Bfused[512,256]^T ; grid.x=4
// FORM 1: commuted. X' = relu([A1|A2][M,512] @ Bfused(K-reinterp) + bias) -> splits+fp16 ; grid.x=2
// FORM 2: like 1 but writes fp32 OUT.
#define GSM 65536
template <int FORM>
__global__ __launch_bounds__(256, 2)
void hmma_gemm_kernel(const __nv_bfloat16* __restrict__ A1hi,
                      const __nv_bfloat16* __restrict__ A1lo,
                      const __nv_bfloat16* __restrict__ A2hi,
                      const __nv_bfloat16* __restrict__ A2lo,
                      const __nv_bfloat16* __restrict__ Bhi,
                      const __nv_bfloat16* __restrict__ Blo,
                      const float* __restrict__ bias,
                      __half* __restrict__ H, float* __restrict__ Y,
                      __nv_bfloat16* __restrict__ XhiN,
                      __nv_bfloat16* __restrict__ XloN,
                      __half* __restrict__ Xf16,
                      float* __restrict__ OUT, int M) {
    constexpr int NCHUNK = (FORM == 0) ? 8 : 16;
    extern __shared__ __align__(1024) uint8_t dsm[];
    const uint32_t base = smem_u32(dsm);

    int t = threadIdx.x;
    int lane = t & 31, wid = t >> 5;
    int wm = wid >> 2;        // 0..1
    int wn = wid & 3;         // 0..3
    int row0 = blockIdx.y * 128;
    int n0   = blockIdx.x * 128;   // FORM0: 0..511 ; FORM1/2: 0..255

    float acc[4][4][4];
    #pragma unroll
    for (int i = 0; i < 4; i++)
        #pragma unroll
        for (int j = 0; j < 4; j++)
            #pragma unroll
            for (int q = 0; q < 4; q++) acc[i][j][q] = 0.f;

    auto load_chunk = [&](int c, int stage) {
        uint32_t sA = base + (uint32_t)stage * 32768u;
        uint32_t sB = sA + 16384u;
        #pragma unroll
        for (int u = 0; u < 4; u++) {
            int idx = t + u * 256;
            int r = idx >> 3;
            int sidx = idx & 7;               // 0-3 hi, 4-7 lo
            uint32_t soff = swz((uint32_t)r * 128 + (uint32_t)sidx * 16);
            int gm = row0 + r;
            size_t grow = (size_t)(gm < M ? gm : 0) * FF;
            const __nv_bfloat16* pa;
            if (FORM == 0 || c < 8) {
                pa = ((sidx < 4) ? A1hi : A1lo) + grow + c * 32 + (sidx & 3) * 8;
            } else {
                pa = ((sidx < 4) ? A2hi : A2lo) + grow + (c - 8) * 32 + (sidx & 3) * 8;
            }
            cp16(sA + soff, pa, (uint32_t)(gm < M));

            int brow, bcol;
            if (FORM == 0) { brow = n0 + r; bcol = c * 32; }
            else { brow = (c < 8) ? (n0 + r) : (256 + n0 + r); bcol = (c & 7) * 32; }
            const __nv_bfloat16* pb = ((sidx < 4) ? Bhi : Blo)
                + (size_t)brow * FF + bcol + (sidx & 3) * 8;
            cp16(sB + soff, pb, 1u);
        }
        CP_COMMIT();
    };

    load_chunk(0, 0);

    for (int c = 0; c < NCHUNK; c++) {
        if (c < NCHUNK - 1) {
            load_chunk(c + 1, (c + 1) & 1);
            cp_wait<1>();
        } else {
            cp_wait<0>();
        }
        __syncthreads();

        uint32_t aAs = base + (uint32_t)(c & 1) * 32768u;
        uint32_t aBs = aAs + 16384u;

        #pragma unroll
        for (int kk = 0; kk < 2; kk++) {
            uint32_t bh[4][2], bl[4][2];
            #pragma unroll
            for (int fnp = 0; fnp < 2; fnp++) {
                uint32_t brow = (uint32_t)(wn * 32 + fnp * 16 + ((lane >> 4) << 3) + (lane & 7));
                uint32_t bseg = (uint32_t)(kk * 2 + ((lane >> 3) & 1));
                uint32_t tmp[4];
                ldmx4(tmp, aBs + swz(brow * 128 + bseg * 16));
                bh[fnp * 2][0] = tmp[0]; bh[fnp * 2][1] = tmp[1];
                bh[fnp * 2 + 1][0] = tmp[2]; bh[fnp * 2 + 1][1] = tmp[3];
                ldmx4(tmp, aBs + swz(brow * 128 + (4 + bseg) * 16));
                bl[fnp * 2][0] = tmp[0]; bl[fnp * 2][1] = tmp[1];
                bl[fnp * 2 + 1][0] = tmp[2]; bl[fnp * 2 + 1][1] = tmp[3];
            }
            #pragma unroll
            for (int fm = 0; fm < 4; fm++) {
                uint32_t arow = (uint32_t)(wm * 64 + fm * 16 + (lane & 15));
                uint32_t aseg = (uint32_t)(kk * 2 + (lane >> 4));
                uint32_t ah[4], al[4];
                ldmx4(ah, aAs + swz(arow * 128 + aseg * 16));
                ldmx4(al, aAs + swz(arow * 128 + (4 + aseg) * 16));
                #pragma unroll
                for (int fn = 0; fn < 4; fn++) {
                    mma16816(acc[fm][fn], ah, bh[fn]);
                    mma16816(acc[fm][fn], ah, bl[fn]);
                    mma16816(acc[fm][fn], al, bh[fn]);
                }
            }
        }
        __syncthreads();
    }

    // ---- epilogue ----
    if (FORM == 0) {
        bool isY = (blockIdx.x >= 2);
        int cb = n0 - (isY ? 256 : 0);
        #pragma unroll
        for (int fm = 0; fm < 4; fm++) {
            int m = row0 + wm * 64 + fm * 16 + (lane >> 2);
            #pragma unroll
            for (int fn = 0; fn < 4; fn++) {
                int col = cb + wn * 32 + fn * 8 + (lane & 3) * 2;
                if (isY) {
                    float2 b2 = *(const float2*)(bias + col);
                    if (m < M) {
                        float2 v = make_float2(acc[fm][fn][0] + b2.x, acc[fm][fn][1] + b2.y);
                        *(float2*)(Y + (size_t)m * FF + col) = v;
                    }
                    if (m + 8 < M) {
                        float2 v = make_float2(acc[fm][fn][2] + b2.x, acc[fm][fn][3] + b2.y);
                        *(float2*)(Y + (size_t)(m + 8) * FF + col) = v;
                    }
                } else {
                    if (m < M)
                        *(__half2*)(H + (size_t)m * FF + col) =
                            __floats2half2_rn(acc[fm][fn][0], acc[fm][fn][1]);
                    if (m + 8 < M)
                        *(__half2*)(H + (size_t)(m + 8) * FF + col) =
                            __floats2half2_rn(acc[fm][fn][2], acc[fm][fn][3]);
                }
            }
        }
    } else {
        #pragma unroll
        for (int fm = 0; fm < 4; fm++) {
            int m = row0 + wm * 64 + fm * 16 + (lane >> 2);
            #pragma unroll
            for (int fn = 0; fn < 4; fn++) {
                int col = n0 + wn * 32 + fn * 8 + (lane & 3) * 2;
                float2 b2 = *(const float2*)(bias + col);
                #pragma unroll
                for (int rr = 0; rr < 2; rr++) {
                    int mm = m + rr * 8;
                    if (mm >= M) continue;
                    float vx = fmaxf(acc[fm][fn][rr * 2 + 0] + b2.x, 0.f);
                    float vy = fmaxf(acc[fm][fn][rr * 2 + 1] + b2.y, 0.f);
                    if (FORM == 2) {
                        *(float2*)(OUT + (size_t)mm * FF + col) = make_float2(vx, vy);
                    } else {
                        __nv_bfloat16 hx = __float2bfloat16(vx);
                        __nv_bfloat16 hy = __float2bfloat16(vy);
                        __nv_bfloat16 lx = __float2bfloat16(vx - __bfloat162float(hx));
                        __nv_bfloat16 ly = __float2bfloat16(vy - __bfloat162float(hy));
                        *(uint32_t*)(XhiN + (size_t)mm * FF + col) = pack_bf16(hx, hy);
                        *(uint32_t*)(XloN + (size_t)mm * FF + col) = pack_bf16(lx, ly);
                        *(__half2*)(Xf16 + (size_t)mm * FF + col) = __floats2half2_rn(vx, vy);
                    }
                }
            }
        }
    }
}

// ---------------- aggregation kernels ----------------
// layer0 (old form): x1 = relu(y + sum w*h[src]); writes x1 splits + fp16
__global__ __launch_bounds__(128)
void agg_old_kernel(__nv_bfloat16* __restrict__ XhiN, __nv_bfloat16* __restrict__ XloN) {
    int n = blockIdx.x * 2 + (threadIdx.x >> 6);
    if (n >= NN) return;
    int f = (threadIdx.x & 63) * 4;

    float4 acc = *(const float4*)(g_y + (size_t)n * FF + f);
    int j = g_rowptr[n], end = g_rowptr[n + 1];

    auto fetch = [&](int s) -> float4 {
        uint2 raw = *(const uint2*)(g_h + (size_t)s * FF + f);
        float2 ab = __half22float2(*(__half2*)&raw.x);
        float2 cd = __half22float2(*(__half2*)&raw.y);
        return make_float4(ab.x, ab.y, cd.x, cd.y);
    };

    for (; j + 4 <= end; j += 4) {
        int s0 = g_csrc[j], s1 = g_csrc[j + 1], s2 = g_csrc[j + 2], s3 = g_csrc[j + 3];
        float w0 = g_cw[j], w1 = g_cw[j + 1], w2 = g_cw[j + 2], w3 = g_cw[j + 3];
        float4 h0 = fetch(s0), h1 = fetch(s1), h2 = fetch(s2), h3 = fetch(s3);
        acc.x = fmaf(w0, h0.x, fmaf(w1, h1.x, fmaf(w2, h2.x, fmaf(w3, h3.x, acc.x))));
        acc.y = fmaf(w0, h0.y, fmaf(w1, h1.y, fmaf(w2, h2.y, fmaf(w3, h3.y, acc.y))));
        acc.z = fmaf(w0, h0.z, fmaf(w1, h1.z, fmaf(w2, h2.z, fmaf(w3, h3.z, acc.z))));
        acc.w = fmaf(w0, h0.w, fmaf(w1, h1.w, fmaf(w2, h2.w, fmaf(w3, h3.w, acc.w))));
    }
    for (; j < end; j++) {
        float w0 = g_cw[j];
        float4 h0 = fetch(g_csrc[j]);
        acc.x = fmaf(w0, h0.x, acc.x);
        acc.y = fmaf(w0, h0.y, acc.y);
        acc.z = fmaf(w0, h0.z, acc.z);
        acc.w = fmaf(w0, h0.w, acc.w);
    }
    acc.x = fmaxf(acc.x, 0.f);
    acc.y = fmaxf(acc.y, 0.f);
    acc.z = fmaxf(acc.z, 0.f);
    acc.w = fmaxf(acc.w, 0.f);

    __nv_bfloat16 h0 = __float2bfloat16(acc.x);
    __nv_bfloat16 h1 = __float2bfloat16(acc.y);
    __nv_bfloat16 h2 = __float2bfloat16(acc.z);
    __nv_bfloat16 h3 = __float2bfloat16(acc.w);
    __nv_bfloat16 l0 = __float2bfloat16(acc.x - __bfloat162float(h0));
    __nv_bfloat16 l1 = __float2bfloat16(acc.y - __bfloat162float(h1));
    __nv_bfloat16 l2 = __float2bfloat16(acc.z - __bfloat162float(h2));
    __nv_bfloat16 l3 = __float2bfloat16(acc.w - __bfloat162float(h3));
    *(uint2*)(XhiN + (size_t)n * FF + f) = make_uint2(pack_bf16(h0, h1), pack_bf16(h2, h3));
    *(uint2*)(XloN + (size_t)n * FF + f) = make_uint2(pack_bf16(l0, l1), pack_bf16(l2, l3));
    uint2 fp;
    *(__half2*)&fp.x = __floats2half2_rn(acc.x, acc.y);
    *(__half2*)&fp.y = __floats2half2_rn(acc.z, acc.w);
    *(uint2*)(g_xf16 + (size_t)n * FF + f) = fp;
}

// commuted form: z = sum w*x[src] (x fp16), write z bf16 splits
__global__ __launch_bounds__(128)
void agg_new_kernel() {
    int n = blockIdx.x * 2 + (threadIdx.x >> 6);
    if (n >= NN) return;
    int f = (threadIdx.x & 63) * 4;

    float4 acc = make_float4(0.f, 0.f, 0.f, 0.f);
    int j = g_rowptr[n], end = g_rowptr[n + 1];

    auto fetch = [&](int s) -> float4 {
        uint2 raw = *(const uint2*)(g_xf16 + (size_t)s * FF + f);
        float2 ab = __half22float2(*(__half2*)&raw.x);
        float2 cd = __half22float2(*(__half2*)&raw.y);
        return make_float4(ab.x, ab.y, cd.x, cd.y);
    };

    for (; j + 4 <= end; j += 4) {
        int s0 = g_csrc[j], s1 = g_csrc[j + 1], s2 = g_csrc[j + 2], s3 = g_csrc[j + 3];
        float w0 = g_cw[j], w1 = g_cw[j + 1], w2 = g_cw[j + 2], w3 = g_cw[j + 3];
        float4 h0 = fetch(s0), h1 = fetch(s1), h2 = fetch(s2), h3 = fetch(s3);
        acc.x = fmaf(w0, h0.x, fmaf(w1, h1.x, fmaf(w2, h2.x, fmaf(w3, h3.x, acc.x))));
        acc.y = fmaf(w0, h0.y, fmaf(w1, h1.y, fmaf(w2, h2.y, fmaf(w3, h3.y, acc.y))));
        acc.z = fmaf(w0, h0.z, fmaf(w1, h1.z, fmaf(w2, h2.z, fmaf(w3, h3.z, acc.z))));
        acc.w = fmaf(w0, h0.w, fmaf(w1, h1.w, fmaf(w2, h2.w, fmaf(w3, h3.w, acc.w))));
    }
    for (; j < end; j++) {
        float w0 = g_cw[j];
        float4 h0 = fetch(g_csrc[j]);
        acc.x = fmaf(w0, h0.x, acc.x);
        acc.y = fmaf(w0, h0.y, acc.y);
        acc.z = fmaf(w0, h0.z, acc.z);
        acc.w = fmaf(w0, h0.w, acc.w);
    }

    __nv_bfloat16 h0 = __float2bfloat16(acc.x);
    __nv_bfloat16 h1 = __float2bfloat16(acc.y);
    __nv_bfloat16 h2 = __float2bfloat16(acc.z);
    __nv_bfloat16 h3 = __float2bfloat16(acc.w);
    __nv_bfloat16 l0 = __float2bfloat16(acc.x - __bfloat162float(h0));
    __nv_bfloat16 l1 = __float2bfloat16(acc.y - __bfloat162float(h1));
    __nv_bfloat16 l2 = __float2bfloat16(acc.z - __bfloat162float(h2));
    __nv_bfloat16 l3 = __float2bfloat16(acc.w - __bfloat162float(h3));
    *(uint2*)(g_zhi + (size_t)n * FF + f) = make_uint2(pack_bf16(h0, h1), pack_bf16(h2, h3));
    *(uint2*)(g_zlo + (size_t)n * FF + f) = make_uint2(pack_bf16(l0, l1), pack_bf16(l2, l3));
}

// ---------------- launch ----------------
extern "C" void kernel_launch(void* const* d_in, const int* in_sizes, int n_in,
                              void* d_out, int out_size) {
    const float* x    = (const float*)d_in[0];
    const int*   ei   = (const int*)d_in[1];
    const float* w    = (const float*)d_in[2];
    const float* Wi   = (const float*)d_in[3];
    const float* Wr   = (const float*)d_in[4];
    const float* bias = (const float*)d_in[5];
    float* out = (float*)d_out;

    const int* src = ei;
    const int* dst = ei + EE;

    void *p_deg, *p_cnt, *p_h, *p_y, *p_zhi, *p_zlo, *p_xf16;
    void *p_xAhi, *p_xAlo, *p_xBhi, *p_xBlo, *p_Bhi, *p_Blo;
    cudaGetSymbolAddress(&p_deg,  g_deg);
    cudaGetSymbolAddress(&p_cnt,  g_cnt);
    cudaGetSymbolAddress(&p_h,    g_h);
    cudaGetSymbolAddress(&p_y,    g_y);
    cudaGetSymbolAddress(&p_zhi,  g_zhi);
    cudaGetSymbolAddress(&p_zlo,  g_zlo);
    cudaGetSymbolAddress(&p_xf16, g_xf16);
    cudaGetSymbolAddress(&p_xAhi, g_xAhi);
    cudaGetSymbolAddress(&p_xAlo, g_xAlo);
    cudaGetSymbolAddress(&p_xBhi, g_xBhi);
    cudaGetSymbolAddress(&p_xBlo, g_xBlo);
    cudaGetSymbolAddress(&p_Bhi,  g_Bhi);
    cudaGetSymbolAddress(&p_Blo,  g_Blo);

    static cudaStream_t s2 = nullptr;
    static cudaEvent_t evFork = nullptr, evW = nullptr, evJoin = nullptr;
    if (!s2) {
        cudaStreamCreateWithFlags(&s2, cudaStreamNonBlocking);
        cudaEventCreateWithFlags(&evFork, cudaEventDisableTiming);
        cudaEventCreateWithFlags(&evW, cudaEventDisableTiming);
        cudaEventCreateWithFlags(&evJoin, cudaEventDisableTiming);
        cudaFuncSetAttribute(hmma_gemm_kernel<0>,
                             cudaFuncAttributeMaxDynamicSharedMemorySize, GSM);
        cudaFuncSetAttribute(hmma_gemm_kernel<1>,
                             cudaFuncAttributeMaxDynamicSharedMemorySize, GSM);
        cudaFuncSetAttribute(hmma_gemm_kernel<2>,
                             cudaFuncAttributeMaxDynamicSharedMemorySize, GSM);
    }

    // ---- fork: weight convert + CSR setup chain on side stream ----
    cudaEventRecord(evFork, 0);
    cudaStreamWaitEvent(s2, evFork, 0);
    convert_w_kernel<<<(3 * 512 * 256 + 255) / 256, 256, 0, s2>>>(Wi, Wr);
    cudaEventRecord(evW, s2);
    cudaMemsetAsync(p_deg, 0, NN * sizeof(float), s2);
    cudaMemsetAsync(p_cnt, 0, NN * sizeof(int), s2);
    hist_kernel<<<(EE + 255) / 256, 256, 0, s2>>>(src, dst, w);
    dinv_kernel<<<(NN + 255) / 256, 256, 0, s2>>>();
    scan_local<<<NB, 256, 0, s2>>>();
    scan_blocks<<<1, 256, 0, s2>>>();
    scan_finish<<<NB, 256, 0, s2>>>();
    fill_kernel<<<(EE + 255) / 256, 256, 0, s2>>>(src, dst, w);
    cudaEventRecord(evJoin, s2);

    // ---- main: split layer-0 activations into set A ----
    convert_x_kernel<<<(NN * FF + 255) / 256, 256>>>(x);
    cudaStreamWaitEvent(0, evW, 0);

    dim3 grid0(4, (NN + 127) / 128);
    dim3 grid1(2, (NN + 127) / 128);
    const int agg_grid = (NN + 1) / 2;

    __nv_bfloat16* xAhi = (__nv_bfloat16*)p_xAhi;
    __nv_bfloat16* xAlo = (__nv_bfloat16*)p_xAlo;
    __nv_bfloat16* xBhi = (__nv_bfloat16*)p_xBhi;
    __nv_bfloat16* xBlo = (__nv_bfloat16*)p_xBlo;
    __nv_bfloat16* zhi  = (__nv_bfloat16*)p_zhi;
    __nv_bfloat16* zlo  = (__nv_bfloat16*)p_zlo;
    const __nv_bfloat16* Bhi = (const __nv_bfloat16*)p_Bhi;
    const __nv_bfloat16* Blo = (const __nv_bfloat16*)p_Blo;

    // ---- layer 0 (old form): GEMM -> agg ----
    hmma_gemm_kernel<0><<<grid0, 256, GSM>>>(
        xAhi, xAlo, nullptr, nullptr, Bhi, Blo, bias,
        (__half*)p_h, (float*)p_y, nullptr, nullptr, nullptr, nullptr, NN);
    cudaStreamWaitEvent(0, evJoin, 0);   // CSR ready before first agg
    agg_old_kernel<<<agg_grid, 128>>>(xBhi, xBlo);   // x1 -> set B + g_xf16

    // ---- layer 1 (commuted): agg -> GEMM(relu fused) ----
    agg_new_kernel<<<agg_grid, 128>>>();             // z = agg(x1)
    hmma_gemm_kernel<1><<<grid1, 256, GSM>>>(
        zhi, zlo, xBhi, xBlo, Bhi + (size_t)1 * 512 * 256, Blo + (size_t)1 * 512 * 256,
        bias + 1 * FF, nullptr, nullptr, xAhi, xAlo, (__half*)p_xf16, nullptr, NN);

    // ---- layer 2 (commuted): agg -> GEMM -> out ----
    agg_new_kernel<<<agg_grid, 128>>>();             // z = agg(x2)
    hmma_gemm_kernel<2><<<grid1, 256, GSM>>>(
        zhi, zlo, xAhi, xAlo, Bhi + (size_t)2 * 512 * 256, Blo + (size_t)2 * 512 * 256,
        bias + 2 * FF, nullptr, nullptr, nullptr, nullptr, nullptr, out, NN);
}

// round 9
// speedup vs baseline: 1.3211x; 1.3211x over previous
#include <cuda_runtime.h>
#include <cuda_fp16.h>
#include <cstdint>
#include <cstddef>

#define NN 50000
#define EE 800000
#define FF 256
#define LL 3
#define NB 196   // ceil(NN/256)

// ---------------- scratch (device globals) ----------------
__device__ float g_deg[NN];
__device__ float g_dinv[NN];
__device__ int   g_cnt[NN];
__device__ int   g_rowptr[NN + 1];
__device__ int   g_cursor[NN];
__device__ int   g_bsum[NB];
__device__ int   g_boff[NB];
__device__ int   g_csrc[EE];
__device__ float g_cw[EE];
__device__ __half g_h[(size_t)NN * FF];      // h = x@Wi in fp16 (agg gather operand)
__device__ float  g_y[(size_t)NN * FF];      // y = x@Wr + b in fp32
__device__ __half g_xf16[(size_t)NN * FF];   // activations in fp16 (GEMM A operand)
// fused transposed weights, fp16 2-term split: [layer][512][256]
// rows 0-255 = Wi^T, rows 256-511 = Wr^T
__device__ __half g_Whi[3 * 512 * 256];
__device__ __half g_Wlo[3 * 512 * 256];

// ---------------- helpers ----------------
__device__ __forceinline__ uint32_t smem_u32(const void* p) {
    uint32_t a;
    asm("{ .reg .u64 t; cvta.to.shared.u64 t, %1; cvt.u32.u64 %0, t; }"
        : "=r"(a) : "l"(p));
    return a;
}
// 64B-row swizzle: XOR row bits into the 16B-segment index
__device__ __forceinline__ uint32_t swz64(uint32_t off) { return off ^ ((off >> 3) & 0x30); }

__device__ __forceinline__ void ldmx4(uint32_t* r, uint32_t addr) {
    asm volatile("ldmatrix.sync.aligned.m8n8.x4.shared.b16 {%0,%1,%2,%3}, [%4];"
                 : "=r"(r[0]), "=r"(r[1]), "=r"(r[2]), "=r"(r[3]) : "r"(addr));
}
__device__ __forceinline__ void mma16816(float* c, const uint32_t* a, const uint32_t* b) {
    asm volatile(
        "mma.sync.aligned.m16n8k16.row.col.f32.f16.f16.f32 "
        "{%0,%1,%2,%3}, {%4,%5,%6,%7}, {%8,%9}, {%0,%1,%2,%3};"
        : "+f"(c[0]), "+f"(c[1]), "+f"(c[2]), "+f"(c[3])
        : "r"(a[0]), "r"(a[1]), "r"(a[2]), "r"(a[3]), "r"(b[0]), "r"(b[1]));
}
__device__ __forceinline__ void cp16(uint32_t dst, const void* src, uint32_t valid) {
    asm volatile("cp.async.cg.shared.global [%0], [%1], 16, %2;"
                 :: "r"(dst), "l"(src), "r"(valid ? 16u : 0u));
}
#define CP_COMMIT() asm volatile("cp.async.commit_group;" ::: "memory")
template <int N> __device__ __forceinline__ void cp_wait() {
    asm volatile("cp.async.wait_group %0;" :: "n"(N) : "memory");
}

// ---------------- setup kernels ----------------
__global__ void hist_kernel(const int* __restrict__ src, const int* __restrict__ dst,
                            const float* __restrict__ w) {
    int e = blockIdx.x * blockDim.x + threadIdx.x;
    if (e >= EE) return;
    int d = dst[e];
    atomicAdd(&g_deg[d], w[e]);
    atomicAdd(&g_cnt[d], 1);
}

__global__ void dinv_kernel() {
    int n = blockIdx.x * blockDim.x + threadIdx.x;
    if (n >= NN) return;
    float d = g_deg[n];
    g_dinv[n] = (d > 0.f) ? rsqrtf(d) : 0.f;
}

__global__ void scan_local() {
    __shared__ int sh[256];
    int b = blockIdx.x, tid = threadIdx.x, i = b * 256 + tid;
    int v = (i < NN) ? g_cnt[i] : 0;
    sh[tid] = v;
    __syncthreads();
    #pragma unroll
    for (int off = 1; off < 256; off <<= 1) {
        int t2 = (tid >= off) ? sh[tid - off] : 0;
        __syncthreads();
        sh[tid] += t2;
        __syncthreads();
    }
    if (i < NN) g_rowptr[i] = sh[tid];
    if (tid == 255) g_bsum[b] = sh[255];
}
__global__ void scan_blocks() {
    __shared__ int sh[256];
    int tid = threadIdx.x;
    int v = (tid < NB) ? g_bsum[tid] : 0;
    sh[tid] = v;
    __syncthreads();
    #pragma unroll
    for (int off = 1; off < 256; off <<= 1) {
        int t2 = (tid >= off) ? sh[tid - off] : 0;
        __syncthreads();
        sh[tid] += t2;
        __syncthreads();
    }
    if (tid < NB) g_boff[tid] = sh[tid] - v;
    if (tid == NB - 1) g_rowptr[NN] = sh[tid];
}
__global__ void scan_finish() {
    int i = blockIdx.x * 256 + threadIdx.x;
    if (i >= NN) return;
    int excl = g_rowptr[i] - g_cnt[i] + g_boff[blockIdx.x];
    g_rowptr[i] = excl;
    g_cursor[i] = excl;
}

__global__ void fill_kernel(const int* __restrict__ src, const int* __restrict__ dst,
                            const float* __restrict__ w) {
    int e = blockIdx.x * blockDim.x + threadIdx.x;
    if (e >= EE) return;
    int s = src[e];
    int d = dst[e];
    int pos = atomicAdd(&g_cursor[d], 1);
    g_csrc[pos] = s;
    g_cw[pos] = g_dinv[s] * w[e] * g_dinv[d];
}

// weights: transpose + fp16 2-term split into fused [l][512][256]
__global__ void convert_w_kernel(const float* __restrict__ Wi, const float* __restrict__ Wr) {
    int idx = blockIdx.x * blockDim.x + threadIdx.x;
    if (idx >= 3 * 512 * 256) return;
    int l = idx >> 17;
    int n = (idx >> 8) & 511;
    int k = idx & 255;
    const float* W = (n < 256) ? Wi : Wr;
    int nn = n & 255;
    float v = W[(size_t)l * FF * FF + (size_t)k * FF + nn];
    __half hi = __float2half(v);
    __half lo = __float2half(v - __half2float(hi));
    g_Whi[idx] = hi;
    g_Wlo[idx] = lo;
}

// layer-0 activations -> fp16
__global__ void convert_x_kernel(const float* __restrict__ x) {
    int idx = blockIdx.x * blockDim.x + threadIdx.x;   // over NN*FF/4
    if (idx >= NN * FF / 4) return;
    float4 v = *(const float4*)(x + idx * 4);
    uint2 p;
    *(__half2*)&p.x = __floats2half2_rn(v.x, v.y);
    *(__half2*)&p.y = __floats2half2_rn(v.z, v.w);
    *(uint2*)(g_xf16 + (size_t)idx * 4) = p;
}

// ---------------- HMMA fp16 GEMM, 2-term weight split (cp.async 2-stage) ----------------
// [H(fp16) | Y(fp32)+bias] = A[M,256](fp16) @ Wfused[512,256]^T(fp16 hi+lo)
// CTA tile 128x128, K-chunk 32. SMEM rows of 64B, swz64. Stage = 8KB A + 8KB Wh + 8KB Wl.
#define GSM 49152
__global__ __launch_bounds__(256, 2)
void hmma_gemm_kernel(const __half* __restrict__ A,
                      const __half* __restrict__ Whi,
                      const __half* __restrict__ Wlo,
                      const float* __restrict__ bias,
                      __half* __restrict__ H, float* __restrict__ Y, int M) {
    extern __shared__ __align__(1024) uint8_t dsm[];
    const uint32_t base = smem_u32(dsm);

    int t = threadIdx.x;
    int lane = t & 31, wid = t >> 5;
    int wm = wid >> 2;        // 0..1
    int wn = wid & 3;         // 0..3
    int row0 = blockIdx.y * 128;
    int nt   = blockIdx.x;    // 0..3 over fused N=512
    int n0   = nt * 128;

    float acc[4][4][4];
    #pragma unroll
    for (int i = 0; i < 4; i++)
        #pragma unroll
        for (int j = 0; j < 4; j++)
            #pragma unroll
            for (int q = 0; q < 4; q++) acc[i][j][q] = 0.f;

    auto load_chunk = [&](int c, int stage) {
        int k0 = c * 32;
        uint32_t sA  = base + (uint32_t)stage * 24576u;
        uint32_t sWh = sA + 8192u;
        uint32_t sWl = sA + 16384u;
        // A: 128 rows x 32 fp16 = 8KB -> 512 cp16
        #pragma unroll
        for (int u = 0; u < 2; u++) {
            int idx = t + u * 256;            // 0..511
            int r = idx >> 2;
            int seg = idx & 3;
            uint32_t soff = swz64((uint32_t)r * 64 + (uint32_t)seg * 16);
            int gm = row0 + r;
            const __half* pa = A + (size_t)(gm < M ? gm : 0) * FF + k0 + seg * 8;
            cp16(sA + soff, pa, (uint32_t)(gm < M));
        }
        // W: hi + lo, each 128 rows x 32 fp16 = 8KB -> 1024 cp16 total
        #pragma unroll
        for (int u = 0; u < 4; u++) {
            int idx = t + u * 256;            // 0..1023
            int r = idx >> 3;
            int sidx = idx & 7;               // 0-3 hi, 4-7 lo
            int seg = sidx & 3;
            uint32_t dstb = (sidx < 4) ? sWh : sWl;
            uint32_t soff = swz64((uint32_t)r * 64 + (uint32_t)seg * 16);
            const __half* pw = ((sidx < 4) ? Whi : Wlo)
                + (size_t)(n0 + r) * FF + k0 + seg * 8;
            cp16(dstb + soff, pw, 1u);
        }
        CP_COMMIT();
    };

    load_chunk(0, 0);

    for (int c = 0; c < 8; c++) {
        if (c < 7) {
            load_chunk(c + 1, (c + 1) & 1);
            cp_wait<1>();
        } else {
            cp_wait<0>();
        }
        __syncthreads();

        uint32_t sA  = base + (uint32_t)(c & 1) * 24576u;
        uint32_t sWh = sA + 8192u;
        uint32_t sWl = sA + 16384u;

        #pragma unroll
        for (int kk = 0; kk < 2; kk++) {
            uint32_t bh[4][2], bl[4][2];
            // B loads: ldmatrix.x4 covers two fn tiles each
            #pragma unroll
            for (int fnp = 0; fnp < 2; fnp++) {
                uint32_t brow = (uint32_t)(wn * 32 + fnp * 16 + ((lane >> 4) << 3) + (lane & 7));
                uint32_t bseg = (uint32_t)(kk * 2 + ((lane >> 3) & 1));
                uint32_t tmp[4];
                ldmx4(tmp, sWh + swz64(brow * 64 + bseg * 16));
                bh[fnp * 2][0] = tmp[0]; bh[fnp * 2][1] = tmp[1];
                bh[fnp * 2 + 1][0] = tmp[2]; bh[fnp * 2 + 1][1] = tmp[3];
                ldmx4(tmp, sWl + swz64(brow * 64 + bseg * 16));
                bl[fnp * 2][0] = tmp[0]; bl[fnp * 2][1] = tmp[1];
                bl[fnp * 2 + 1][0] = tmp[2]; bl[fnp * 2 + 1][1] = tmp[3];
            }
            #pragma unroll
            for (int fm = 0; fm < 4; fm++) {
                uint32_t arow = (uint32_t)(wm * 64 + fm * 16 + (lane & 15));
                uint32_t aseg = (uint32_t)(kk * 2 + (lane >> 4));
                uint32_t ah[4];
                ldmx4(ah, sA + swz64(arow * 64 + aseg * 16));
                #pragma unroll
                for (int fn = 0; fn < 4; fn++) {
                    mma16816(acc[fm][fn], ah, bh[fn]);
                    mma16816(acc[fm][fn], ah, bl[fn]);
                }
            }
        }
        __syncthreads();
    }

    // ---- epilogue: H fp16 (cols 0-255) | Y fp32 + bias (cols 256-511) ----
    bool isY = (nt >= 2);
    int cb = n0 - (isY ? 256 : 0);

    #pragma unroll
    for (int fm = 0; fm < 4; fm++) {
        int m = row0 + wm * 64 + fm * 16 + (lane >> 2);
        #pragma unroll
        for (int fn = 0; fn < 4; fn++) {
            int col = cb + wn * 32 + fn * 8 + (lane & 3) * 2;
            if (isY) {
                float2 b2 = *(const float2*)(bias + col);
                if (m < M) {
                    float2 v = make_float2(acc[fm][fn][0] + b2.x, acc[fm][fn][1] + b2.y);
                    *(float2*)(Y + (size_t)m * FF + col) = v;
                }
                if (m + 8 < M) {
                    float2 v = make_float2(acc[fm][fn][2] + b2.x, acc[fm][fn][3] + b2.y);
                    *(float2*)(Y + (size_t)(m + 8) * FF + col) = v;
                }
            } else {
                if (m < M)
                    *(__half2*)(H + (size_t)m * FF + col) =
                        __floats2half2_rn(acc[fm][fn][0], acc[fm][fn][1]);
                if (m + 8 < M)
                    *(__half2*)(H + (size_t)(m + 8) * FF + col) =
                        __floats2half2_rn(acc[fm][fn][2], acc[fm][fn][3]);
            }
        }
    }
}

// ---------------- aggregation ----------------
// xnext[n,f] = relu(y[n,f] + sum_j cw[j]*h[csrc[j],f]), h in fp16
// MODE 0: write fp16 into g_xf16 (next GEMM A). MODE 1: write fp32 out.
template <int MODE>
__global__ __launch_bounds__(128)
void agg_kernel(float* __restrict__ xnext) {
    int n = blockIdx.x * 2 + (threadIdx.x >> 6);
    if (n >= NN) return;
    int f = (threadIdx.x & 63) * 4;

    float4 acc = *(const float4*)(g_y + (size_t)n * FF + f);
    int j = g_rowptr[n], end = g_rowptr[n + 1];

    auto fetch = [&](int s) -> float4 {
        uint2 raw = *(const uint2*)(g_h + (size_t)s * FF + f);
        float2 ab = __half22float2(*(__half2*)&raw.x);
        float2 cd = __half22float2(*(__half2*)&raw.y);
        return make_float4(ab.x, ab.y, cd.x, cd.y);
    };

    for (; j + 4 <= end; j += 4) {
        int s0 = g_csrc[j], s1 = g_csrc[j + 1], s2 = g_csrc[j + 2], s3 = g_csrc[j + 3];
        float w0 = g_cw[j], w1 = g_cw[j + 1], w2 = g_cw[j + 2], w3 = g_cw[j + 3];
        float4 h0 = fetch(s0), h1 = fetch(s1), h2 = fetch(s2), h3 = fetch(s3);
        acc.x = fmaf(w0, h0.x, fmaf(w1, h1.x, fmaf(w2, h2.x, fmaf(w3, h3.x, acc.x))));
        acc.y = fmaf(w0, h0.y, fmaf(w1, h1.y, fmaf(w2, h2.y, fmaf(w3, h3.y, acc.y))));
        acc.z = fmaf(w0, h0.z, fmaf(w1, h1.z, fmaf(w2, h2.z, fmaf(w3, h3.z, acc.z))));
        acc.w = fmaf(w0, h0.w, fmaf(w1, h1.w, fmaf(w2, h2.w, fmaf(w3, h3.w, acc.w))));
    }
    for (; j < end; j++) {
        float w0 = g_cw[j];
        float4 h0 = fetch(g_csrc[j]);
        acc.x = fmaf(w0, h0.x, acc.x);
        acc.y = fmaf(w0, h0.y, acc.y);
        acc.z = fmaf(w0, h0.z, acc.z);
        acc.w = fmaf(w0, h0.w, acc.w);
    }
    acc.x = fmaxf(acc.x, 0.f);
    acc.y = fmaxf(acc.y, 0.f);
    acc.z = fmaxf(acc.z, 0.f);
    acc.w = fmaxf(acc.w, 0.f);

    if (MODE == 1) {
        *(float4*)(xnext + (size_t)n * FF + f) = acc;
    } else {
        uint2 p;
        *(__half2*)&p.x = __floats2half2_rn(acc.x, acc.y);
        *(__half2*)&p.y = __floats2half2_rn(acc.z, acc.w);
        *(uint2*)(g_xf16 + (size_t)n * FF + f) = p;
    }
}

// ---------------- launch ----------------
extern "C" void kernel_launch(void* const* d_in, const int* in_sizes, int n_in,
                              void* d_out, int out_size) {
    const float* x    = (const float*)d_in[0];
    const int*   ei   = (const int*)d_in[1];
    const float* w    = (const float*)d_in[2];
    const float* Wi   = (const float*)d_in[3];
    const float* Wr   = (const float*)d_in[4];
    const float* bias = (const float*)d_in[5];
    float* out = (float*)d_out;

    const int* src = ei;
    const int* dst = ei + EE;

    void *p_deg, *p_cnt, *p_h, *p_y, *p_xf16, *p_Whi, *p_Wlo;
    cudaGetSymbolAddress(&p_deg,  g_deg);
    cudaGetSymbolAddress(&p_cnt,  g_cnt);
    cudaGetSymbolAddress(&p_h,    g_h);
    cudaGetSymbolAddress(&p_y,    g_y);
    cudaGetSymbolAddress(&p_xf16, g_xf16);
    cudaGetSymbolAddress(&p_Whi,  g_Whi);
    cudaGetSymbolAddress(&p_Wlo,  g_Wlo);

    static cudaStream_t s2 = nullptr;
    static cudaEvent_t evFork = nullptr, evW = nullptr, evJoin = nullptr;
    if (!s2) {
        cudaStreamCreateWithFlags(&s2, cudaStreamNonBlocking);
        cudaEventCreateWithFlags(&evFork, cudaEventDisableTiming);
        cudaEventCreateWithFlags(&evW, cudaEventDisableTiming);
        cudaEventCreateWithFlags(&evJoin, cudaEventDisableTiming);
        cudaFuncSetAttribute(hmma_gemm_kernel,
                             cudaFuncAttributeMaxDynamicSharedMemorySize, GSM);
    }

    // ---- fork: weight convert + CSR setup chain on side stream ----
    cudaEventRecord(evFork, 0);
    cudaStreamWaitEvent(s2, evFork, 0);
    convert_w_kernel<<<(3 * 512 * 256 + 255) / 256, 256, 0, s2>>>(Wi, Wr);
    cudaEventRecord(evW, s2);
    cudaMemsetAsync(p_deg, 0, NN * sizeof(float), s2);
    cudaMemsetAsync(p_cnt, 0, NN * sizeof(int), s2);
    hist_kernel<<<(EE + 255) / 256, 256, 0, s2>>>(src, dst, w);
    dinv_kernel<<<(NN + 255) / 256, 256, 0, s2>>>();
    scan_local<<<NB, 256, 0, s2>>>();
    scan_blocks<<<1, 256, 0, s2>>>();
    scan_finish<<<NB, 256, 0, s2>>>();
    fill_kernel<<<(EE + 255) / 256, 256, 0, s2>>>(src, dst, w);
    cudaEventRecord(evJoin, s2);

    // ---- main: layer-0 activations -> fp16 ----
    convert_x_kernel<<<(NN * FF / 4 + 255) / 256, 256>>>(x);
    cudaStreamWaitEvent(0, evW, 0);

    dim3 ggrid(4, (NN + 127) / 128);
    const __half* Whi = (const __half*)p_Whi;
    const __half* Wlo = (const __half*)p_Wlo;

    for (int l = 0; l < LL; l++) {
        const float* bl = bias + (size_t)l * FF;

        hmma_gemm_kernel<<<ggrid, 256, GSM>>>((const __half*)p_xf16,
                                              Whi + (size_t)l * 512 * 256,
                                              Wlo + (size_t)l * 512 * 256,
                                              bl, (__half*)p_h, (float*)p_y, NN);
        if (l == 0) cudaStreamWaitEvent(0, evJoin, 0);   // CSR ready before first agg
        if (l < LL - 1)
            agg_kernel<0><<<(NN + 1) / 2, 128>>>(nullptr);
        else
            agg_kernel<1><<<(NN + 1) / 2, 128>>>(out);
    }
}

// round 10
// speedup vs baseline: 1.4614x; 1.1062x over previous
#include <cuda_runtime.h>
#include <cuda_fp16.h>
#include <cstdint>
#include <cstddef>

#define NN 50000
#define EE 800000
#define FF 256
#define LL 3
#define NB 196   // ceil(NN/256)

// ---------------- scratch (device globals) ----------------
__device__ float g_deg[NN];
__device__ float g_dinv[NN];
__device__ int   g_cnt[NN];
__device__ int   g_rowptr[NN + 1];
__device__ int   g_cursor[NN];
__device__ int   g_bsum[NB];
__device__ int   g_boff[NB];
__device__ int   g_csrc[EE];
__device__ float g_cw[EE];
__device__ __half g_h[(size_t)NN * FF];      // h = x@Wi in fp16 (agg gather operand)
__device__ float  g_y[(size_t)NN * FF];      // y = x@Wr + b in fp32
__device__ __half g_xf16[(size_t)NN * FF];   // activations in fp16 (GEMM A operand)
// fused transposed weights, fp16 2-term split: [layer][512][256]
// rows 0-255 = Wi^T, rows 256-511 = Wr^T
__device__ __half g_Whi[3 * 512 * 256];
__device__ __half g_Wlo[3 * 512 * 256];

// ---------------- helpers ----------------
__device__ __forceinline__ uint32_t smem_u32(const void* p) {
    uint32_t a;
    asm("{ .reg .u64 t; cvta.to.shared.u64 t, %1; cvt.u32.u64 %0, t; }"
        : "=r"(a) : "l"(p));
    return a;
}
// 64B-row swizzle
__device__ __forceinline__ uint32_t swz64(uint32_t off) { return off ^ ((off >> 3) & 0x30); }

__device__ __forceinline__ void ldmx4(uint32_t* r, uint32_t addr) {
    asm volatile("ldmatrix.sync.aligned.m8n8.x4.shared.b16 {%0,%1,%2,%3}, [%4];"
                 : "=r"(r[0]), "=r"(r[1]), "=r"(r[2]), "=r"(r[3]) : "r"(addr));
}
__device__ __forceinline__ void mma16816(float* c, const uint32_t* a, const uint32_t* b) {
    asm volatile(
        "mma.sync.aligned.m16n8k16.row.col.f32.f16.f16.f32 "
        "{%0,%1,%2,%3}, {%4,%5,%6,%7}, {%8,%9}, {%0,%1,%2,%3};"
        : "+f"(c[0]), "+f"(c[1]), "+f"(c[2]), "+f"(c[3])
        : "r"(a[0]), "r"(a[1]), "r"(a[2]), "r"(a[3]), "r"(b[0]), "r"(b[1]));
}
__device__ __forceinline__ void cp16(uint32_t dst, const void* src, uint32_t valid) {
    asm volatile("cp.async.cg.shared.global [%0], [%1], 16, %2;"
                 :: "r"(dst), "l"(src), "r"(valid ? 16u : 0u));
}
#define CP_COMMIT() asm volatile("cp.async.commit_group;" ::: "memory")
template <int N> __device__ __forceinline__ void cp_wait() {
    asm volatile("cp.async.wait_group %0;" :: "n"(N) : "memory");
}

// ---------------- setup kernels ----------------
__global__ void hist_kernel(const int* __restrict__ src, const int* __restrict__ dst,
                            const float* __restrict__ w) {
    int e = blockIdx.x * blockDim.x + threadIdx.x;
    if (e >= EE) return;
    int d = dst[e];
    atomicAdd(&g_deg[d], w[e]);
    atomicAdd(&g_cnt[d], 1);
}

__global__ void dinv_kernel() {
    int n = blockIdx.x * blockDim.x + threadIdx.x;
    if (n >= NN) return;
    float d = g_deg[n];
    g_dinv[n] = (d > 0.f) ? rsqrtf(d) : 0.f;
}

__global__ void scan_local() {
    __shared__ int sh[256];
    int b = blockIdx.x, tid = threadIdx.x, i = b * 256 + tid;
    int v = (i < NN) ? g_cnt[i] : 0;
    sh[tid] = v;
    __syncthreads();
    #pragma unroll
    for (int off = 1; off < 256; off <<= 1) {
        int t2 = (tid >= off) ? sh[tid - off] : 0;
        __syncthreads();
        sh[tid] += t2;
        __syncthreads();
    }
    if (i < NN) g_rowptr[i] = sh[tid];
    if (tid == 255) g_bsum[b] = sh[255];
}
__global__ void scan_blocks() {
    __shared__ int sh[256];
    int tid = threadIdx.x;
    int v = (tid < NB) ? g_bsum[tid] : 0;
    sh[tid] = v;
    __syncthreads();
    #pragma unroll
    for (int off = 1; off < 256; off <<= 1) {
        int t2 = (tid >= off) ? sh[tid - off] : 0;
        __syncthreads();
        sh[tid] += t2;
        __syncthreads();
    }
    if (tid < NB) g_boff[tid] = sh[tid] - v;
    if (tid == NB - 1) g_rowptr[NN] = sh[tid];
}
__global__ void scan_finish() {
    int i = blockIdx.x * 256 + threadIdx.x;
    if (i >= NN) return;
    int excl = g_rowptr[i] - g_cnt[i] + g_boff[blockIdx.x];
    g_rowptr[i] = excl;
    g_cursor[i] = excl;
}

__global__ void fill_kernel(const int* __restrict__ src, const int* __restrict__ dst,
                            const float* __restrict__ w) {
    int e = blockIdx.x * blockDim.x + threadIdx.x;
    if (e >= EE) return;
    int s = src[e];
    int d = dst[e];
    int pos = atomicAdd(&g_cursor[d], 1);
    g_csrc[pos] = s;
    g_cw[pos] = g_dinv[s] * w[e] * g_dinv[d];
}

// weights: transpose + fp16 2-term split into fused [l][512][256]
__global__ void convert_w_kernel(const float* __restrict__ Wi, const float* __restrict__ Wr) {
    int idx = blockIdx.x * blockDim.x + threadIdx.x;
    if (idx >= 3 * 512 * 256) return;
    int l = idx >> 17;
    int n = (idx >> 8) & 511;
    int k = idx & 255;
    const float* W = (n < 256) ? Wi : Wr;
    int nn = n & 255;
    float v = W[(size_t)l * FF * FF + (size_t)k * FF + nn];
    __half hi = __float2half(v);
    __half lo = __float2half(v - __half2float(hi));
    g_Whi[idx] = hi;
    g_Wlo[idx] = lo;
}

// layer-0 activations -> fp16
__global__ void convert_x_kernel(const float* __restrict__ x) {
    int idx = blockIdx.x * blockDim.x + threadIdx.x;   // over NN*FF/4
    if (idx >= NN * FF / 4) return;
    float4 v = *(const float4*)(x + idx * 4);
    uint2 p;
    *(__half2*)&p.x = __floats2half2_rn(v.x, v.y);
    *(__half2*)&p.y = __floats2half2_rn(v.z, v.w);
    *(uint2*)(g_xf16 + (size_t)idx * 4) = p;
}

// ---------------- HMMA fp16 GEMM (cp.async 2-stage) ----------------
// TERMS=1: H(fp16) = A @ Wi^T (hi only); W rows [0,256). grid.x=2
// TERMS=2: Y(fp32)+bias = A @ Wr^T (hi+lo); W rows [256,512). grid.x=2, ntBase=2
// CTA tile 128x128, K-chunk 32, SMEM rows 64B swz64.
#define GSM1 32768
#define GSM2 49152
template <int TERMS>
__global__ __launch_bounds__(256, 2)
void hmma_gemm_kernel(const __half* __restrict__ A,
                      const __half* __restrict__ Whi,
                      const __half* __restrict__ Wlo,
                      const float* __restrict__ bias,
                      __half* __restrict__ H, float* __restrict__ Y,
                      int M, int ntBase) {
    constexpr uint32_t STAGE = (TERMS == 2) ? 24576u : 16384u;
    extern __shared__ __align__(1024) uint8_t dsm[];
    const uint32_t base = smem_u32(dsm);

    int t = threadIdx.x;
    int lane = t & 31, wid = t >> 5;
    int wm = wid >> 2;        // 0..1
    int wn = wid & 3;         // 0..3
    int row0 = blockIdx.y * 128;
    int nt   = ntBase + blockIdx.x;
    int n0   = nt * 128;      // fused W row base

    float acc[4][4][4];
    #pragma unroll
    for (int i = 0; i < 4; i++)
        #pragma unroll
        for (int j = 0; j < 4; j++)
            #pragma unroll
            for (int q = 0; q < 4; q++) acc[i][j][q] = 0.f;

    auto load_chunk = [&](int c, int stage) {
        int k0 = c * 32;
        uint32_t sA  = base + (uint32_t)stage * STAGE;
        uint32_t sWh = sA + 8192u;
        uint32_t sWl = sA + 16384u;
        #pragma unroll
        for (int u = 0; u < 2; u++) {
            int idx = t + u * 256;            // 0..511 = 128 rows x 4 segs
            int r = idx >> 2;
            int seg = idx & 3;
            uint32_t soff = swz64((uint32_t)r * 64 + (uint32_t)seg * 16);
            int gm = row0 + r;
            const __half* pa = A + (size_t)(gm < M ? gm : 0) * FF + k0 + seg * 8;
            cp16(sA + soff, pa, (uint32_t)(gm < M));
            const __half* ph = Whi + (size_t)(n0 + r) * FF + k0 + seg * 8;
            cp16(sWh + soff, ph, 1u);
            if (TERMS == 2) {
                const __half* pl = Wlo + (size_t)(n0 + r) * FF + k0 + seg * 8;
                cp16(sWl + soff, pl, 1u);
            }
        }
        CP_COMMIT();
    };

    load_chunk(0, 0);

    for (int c = 0; c < 8; c++) {
        if (c < 7) {
            load_chunk(c + 1, (c + 1) & 1);
            cp_wait<1>();
        } else {
            cp_wait<0>();
        }
        __syncthreads();

        uint32_t sA  = base + (uint32_t)(c & 1) * STAGE;
        uint32_t sWh = sA + 8192u;
        uint32_t sWl = sA + 16384u;

        #pragma unroll
        for (int kk = 0; kk < 2; kk++) {
            uint32_t bh[4][2], bl[4][2];
            #pragma unroll
            for (int fnp = 0; fnp < 2; fnp++) {
                uint32_t brow = (uint32_t)(wn * 32 + fnp * 16 + ((lane >> 4) << 3) + (lane & 7));
                uint32_t bseg = (uint32_t)(kk * 2 + ((lane >> 3) & 1));
                uint32_t tmp[4];
                ldmx4(tmp, sWh + swz64(brow * 64 + bseg * 16));
                bh[fnp * 2][0] = tmp[0]; bh[fnp * 2][1] = tmp[1];
                bh[fnp * 2 + 1][0] = tmp[2]; bh[fnp * 2 + 1][1] = tmp[3];
                if (TERMS == 2) {
                    ldmx4(tmp, sWl + swz64(brow * 64 + bseg * 16));
                    bl[fnp * 2][0] = tmp[0]; bl[fnp * 2][1] = tmp[1];
                    bl[fnp * 2 + 1][0] = tmp[2]; bl[fnp * 2 + 1][1] = tmp[3];
                }
            }
            #pragma unroll
            for (int fm = 0; fm < 4; fm++) {
                uint32_t arow = (uint32_t)(wm * 64 + fm * 16 + (lane & 15));
                uint32_t aseg = (uint32_t)(kk * 2 + (lane >> 4));
                uint32_t ah[4];
                ldmx4(ah, sA + swz64(arow * 64 + aseg * 16));
                #pragma unroll
                for (int fn = 0; fn < 4; fn++) {
                    mma16816(acc[fm][fn], ah, bh[fn]);
                    if (TERMS == 2) mma16816(acc[fm][fn], ah, bl[fn]);
                }
            }
        }
        __syncthreads();
    }

    // ---- epilogue ----
    #pragma unroll
    for (int fm = 0; fm < 4; fm++) {
        int m = row0 + wm * 64 + fm * 16 + (lane >> 2);
        #pragma unroll
        for (int fn = 0; fn < 4; fn++) {
            if (TERMS == 2) {
                int col = (n0 - 256) + wn * 32 + fn * 8 + (lane & 3) * 2;
                float2 b2 = *(const float2*)(bias + col);
                if (m < M) {
                    float2 v = make_float2(acc[fm][fn][0] + b2.x, acc[fm][fn][1] + b2.y);
                    *(float2*)(Y + (size_t)m * FF + col) = v;
                }
                if (m + 8 < M) {
                    float2 v = make_float2(acc[fm][fn][2] + b2.x, acc[fm][fn][3] + b2.y);
                    *(float2*)(Y + (size_t)(m + 8) * FF + col) = v;
                }
            } else {
                int col = n0 + wn * 32 + fn * 8 + (lane & 3) * 2;
                if (m < M)
                    *(__half2*)(H + (size_t)m * FF + col) =
                        __floats2half2_rn(acc[fm][fn][0], acc[fm][fn][1]);
                if (m + 8 < M)
                    *(__half2*)(H + (size_t)(m + 8) * FF + col) =
                        __floats2half2_rn(acc[fm][fn][2], acc[fm][fn][3]);
            }
        }
    }
}

// ---------------- aggregation ----------------
// xnext[n,f] = relu(y[n,f] + sum_j cw[j]*h[csrc[j],f]), h fp16
// MODE 0: write fp16 into g_xf16 (next GEMM A). MODE 1: write fp32 out.
template <int MODE>
__global__ __launch_bounds__(128)
void agg_kernel(float* __restrict__ xnext) {
    int n = blockIdx.x * 2 + (threadIdx.x >> 6);
    if (n >= NN) return;
    int f = (threadIdx.x & 63) * 4;

    float4 acc = *(const float4*)(g_y + (size_t)n * FF + f);
    int j = g_rowptr[n], end = g_rowptr[n + 1];

    auto fetch = [&](int s) -> float4 {
        uint2 raw = *(const uint2*)(g_h + (size_t)s * FF + f);
        float2 ab = __half22float2(*(__half2*)&raw.x);
        float2 cd = __half22float2(*(__half2*)&raw.y);
        return make_float4(ab.x, ab.y, cd.x, cd.y);
    };

    for (; j + 4 <= end; j += 4) {
        int s0 = g_csrc[j], s1 = g_csrc[j + 1], s2 = g_csrc[j + 2], s3 = g_csrc[j + 3];
        float w0 = g_cw[j], w1 = g_cw[j + 1], w2 = g_cw[j + 2], w3 = g_cw[j + 3];
        float4 h0 = fetch(s0), h1 = fetch(s1), h2 = fetch(s2), h3 = fetch(s3);
        acc.x = fmaf(w0, h0.x, fmaf(w1, h1.x, fmaf(w2, h2.x, fmaf(w3, h3.x, acc.x))));
        acc.y = fmaf(w0, h0.y, fmaf(w1, h1.y, fmaf(w2, h2.y, fmaf(w3, h3.y, acc.y))));
        acc.z = fmaf(w0, h0.z, fmaf(w1, h1.z, fmaf(w2, h2.z, fmaf(w3, h3.z, acc.z))));
        acc.w = fmaf(w0, h0.w, fmaf(w1, h1.w, fmaf(w2, h2.w, fmaf(w3, h3.w, acc.w))));
    }
    for (; j < end; j++) {
        float w0 = g_cw[j];
        float4 h0 = fetch(g_csrc[j]);
        acc.x = fmaf(w0, h0.x, acc.x);
        acc.y = fmaf(w0, h0.y, acc.y);
        acc.z = fmaf(w0, h0.z, acc.z);
        acc.w = fmaf(w0, h0.w, acc.w);
    }
    acc.x = fmaxf(acc.x, 0.f);
    acc.y = fmaxf(acc.y, 0.f);
    acc.z = fmaxf(acc.z, 0.f);
    acc.w = fmaxf(acc.w, 0.f);

    if (MODE == 1) {
        *(float4*)(xnext + (size_t)n * FF + f) = acc;
    } else {
        uint2 p;
        *(__half2*)&p.x = __floats2half2_rn(acc.x, acc.y);
        *(__half2*)&p.y = __floats2half2_rn(acc.z, acc.w);
        *(uint2*)(g_xf16 + (size_t)n * FF + f) = p;
    }
}

// ---------------- launch ----------------
extern "C" void kernel_launch(void* const* d_in, const int* in_sizes, int n_in,
                              void* d_out, int out_size) {
    const float* x    = (const float*)d_in[0];
    const int*   ei   = (const int*)d_in[1];
    const float* w    = (const float*)d_in[2];
    const float* Wi   = (const float*)d_in[3];
    const float* Wr   = (const float*)d_in[4];
    const float* bias = (const float*)d_in[5];
    float* out = (float*)d_out;

    const int* src = ei;
    const int* dst = ei + EE;

    void *p_deg, *p_cnt, *p_h, *p_y, *p_xf16, *p_Whi, *p_Wlo;
    cudaGetSymbolAddress(&p_deg,  g_deg);
    cudaGetSymbolAddress(&p_cnt,  g_cnt);
    cudaGetSymbolAddress(&p_h,    g_h);
    cudaGetSymbolAddress(&p_y,    g_y);
    cudaGetSymbolAddress(&p_xf16, g_xf16);
    cudaGetSymbolAddress(&p_Whi,  g_Whi);
    cudaGetSymbolAddress(&p_Wlo,  g_Wlo);

    static cudaStream_t s2 = nullptr;
    static cudaEvent_t evFork = nullptr, evW = nullptr, evJoin = nullptr;
    if (!s2) {
        cudaStreamCreateWithFlags(&s2, cudaStreamNonBlocking);
        cudaEventCreateWithFlags(&evFork, cudaEventDisableTiming);
        cudaEventCreateWithFlags(&evW, cudaEventDisableTiming);
        cudaEventCreateWithFlags(&evJoin, cudaEventDisableTiming);
        cudaFuncSetAttribute(hmma_gemm_kernel<1>,
                             cudaFuncAttributeMaxDynamicSharedMemorySize, GSM1);
        cudaFuncSetAttribute(hmma_gemm_kernel<2>,
                             cudaFuncAttributeMaxDynamicSharedMemorySize, GSM2);
    }

    // ---- fork: weight convert + CSR setup chain on side stream ----
    cudaEventRecord(evFork, 0);
    cudaStreamWaitEvent(s2, evFork, 0);
    convert_w_kernel<<<(3 * 512 * 256 + 255) / 256, 256, 0, s2>>>(Wi, Wr);
    cudaEventRecord(evW, s2);
    cudaMemsetAsync(p_deg, 0, NN * sizeof(float), s2);
    cudaMemsetAsync(p_cnt, 0, NN * sizeof(int), s2);
    hist_kernel<<<(EE + 255) / 256, 256, 0, s2>>>(src, dst, w);
    dinv_kernel<<<(NN + 255) / 256, 256, 0, s2>>>();
    scan_local<<<NB, 256, 0, s2>>>();
    scan_blocks<<<1, 256, 0, s2>>>();
    scan_finish<<<NB, 256, 0, s2>>>();
    fill_kernel<<<(EE + 255) / 256, 256, 0, s2>>>(src, dst, w);
    cudaEventRecord(evJoin, s2);

    // ---- main: layer-0 activations -> fp16 ----
    convert_x_kernel<<<(NN * FF / 4 + 255) / 256, 256>>>(x);
    cudaStreamWaitEvent(0, evW, 0);

    dim3 ggrid(2, (NN + 127) / 128);
    const __half* Whi = (const __half*)p_Whi;
    const __half* Wlo = (const __half*)p_Wlo;

    for (int l = 0; l < LL; l++) {
        const float* bl = bias + (size_t)l * FF;
        const __half* Whl = Whi + (size_t)l * 512 * 256;
        const __half* Wll = Wlo + (size_t)l * 512 * 256;

        // H = A @ Wi^T (1-term, fp16 out), W rows [0,256)
        hmma_gemm_kernel<1><<<ggrid, 256, GSM1>>>((const __half*)p_xf16, Whl, nullptr,
                                                  nullptr, (__half*)p_h, nullptr, NN, 0);
        // Y = A @ Wr^T + b (2-term, fp32 out), W rows [256,512)
        hmma_gemm_kernel<2><<<ggrid, 256, GSM2>>>((const __half*)p_xf16, Whl, Wll,
                                                  bl, nullptr, (float*)p_y, NN, 2);
        if (l == 0) cudaStreamWaitEvent(0, evJoin, 0);   // CSR ready before first agg
        if (l < LL - 1)
            agg_kernel<0><<<(NN + 1) / 2, 128>>>(nullptr);
        else
            agg_kernel<1><<<(NN + 1) / 2, 128>>>(out);
    }
}